// round 1
// baseline (speedup 1.0000x reference)
#include <cuda_runtime.h>

#define BATCH   1024
#define SENS    128
#define NSTATE  256
#define MOUT    32
#define NUNFOLD 6
#define BB      8         // batch rows per block
#define EPSV    1e-8f

// Packed params: x=-sigma*log2e, y=sigma*mu*log2e, z=w*mask, w=w*erev*mask
__device__ float4 g_params[NSTATE * NSTATE];
__device__ float4 g_sparams[SENS * NSTATE];

__device__ __forceinline__ float fex2(float x) {
    float y; asm("ex2.approx.ftz.f32 %0, %1;" : "=f"(y) : "f"(x)); return y;
}
__device__ __forceinline__ float frcp(float x) {
    float y; asm("rcp.approx.ftz.f32 %0, %1;" : "=f"(y) : "f"(x)); return y;
}

__global__ void pack_kernel(const float* __restrict__ sigma, const float* __restrict__ mu,
                            const float* __restrict__ w,     const float* __restrict__ erev,
                            const float* __restrict__ mask,
                            const float* __restrict__ ssigma, const float* __restrict__ smu,
                            const float* __restrict__ sw,     const float* __restrict__ serev,
                            const float* __restrict__ smask)
{
    const float L2E = 1.4426950408889634f;
    int idx = blockIdx.x * blockDim.x + threadIdx.x;
    if (idx < NSTATE * NSTATE) {
        float sg = sigma[idx] * L2E;
        float wm = w[idx] * mask[idx];
        g_params[idx] = make_float4(-sg, sg * mu[idx], wm, w[idx] * erev[idx] * mask[idx]);
    }
    if (idx < SENS * NSTATE) {
        float sg = ssigma[idx] * L2E;
        float wm = sw[idx] * smask[idx];
        g_sparams[idx] = make_float4(-sg, sg * smu[idx], wm, sw[idx] * serev[idx] * smask[idx]);
    }
}

__global__ __launch_bounds__(NSTATE, 1)
void ltc_kernel(const float* __restrict__ inputs, const float* __restrict__ states,
                const float* __restrict__ gleak,  const float* __restrict__ vleak,
                const float* __restrict__ cm,
                const float* __restrict__ input_w, const float* __restrict__ input_b,
                const float* __restrict__ output_w, const float* __restrict__ output_b,
                float* __restrict__ out)
{
    __shared__ float sx[BB][SENS];       // mapped sensory inputs
    __shared__ float sv[BB][NSTATE];     // current state

    const int j  = threadIdx.x;          // output neuron index
    const int b0 = blockIdx.x * BB;      // first batch row of this block

    // Load inputs with affine mapping into shared
    for (int t = threadIdx.x; t < BB * SENS; t += blockDim.x) {
        int bb = t / SENS, s = t % SENS;
        sx[bb][s] = inputs[(b0 + bb) * SENS + s] * input_w[s] + input_b[s];
    }
    // Load states into shared
    #pragma unroll
    for (int bb = 0; bb < BB; bb++)
        sv[bb][j] = states[(b0 + bb) * NSTATE + j];
    __syncthreads();

    // ---- Sensory synapse reduction (computed once) ----
    float snum[BB], sden[BB];
    #pragma unroll
    for (int bb = 0; bb < BB; bb++) { snum[bb] = 0.0f; sden[bb] = 0.0f; }

    #pragma unroll 2
    for (int s = 0; s < SENS; s++) {
        float4 p = g_sparams[s * NSTATE + j];
        #pragma unroll
        for (int bb = 0; bb < BB; bb++) {
            float e = fex2(fmaf(p.x, sx[bb][s], p.y));   // exp(-sigma*(x-mu))
            float r = frcp(1.0f + e);                    // sigmoid
            sden[bb] = fmaf(p.z, r, sden[bb]);
            snum[bb] = fmaf(p.w, r, snum[bb]);
        }
    }

    // Per-neuron constants
    const float gl  = gleak[j];
    const float gv  = gl * vleak[j];
    const float cmt = cm[j] * (float)NUNFOLD;   // cm / (DT/UNFOLDS), DT = 1

    // ---- Unfold loop ----
    for (int u = 0; u < NUNFOLD; u++) {
        float num[BB], den[BB];
        #pragma unroll
        for (int bb = 0; bb < BB; bb++) { num[bb] = snum[bb]; den[bb] = sden[bb]; }

        #pragma unroll 2
        for (int i = 0; i < NSTATE; i++) {
            float4 p = g_params[i * NSTATE + j];
            #pragma unroll
            for (int bb = 0; bb < BB; bb++) {
                float e = fex2(fmaf(p.x, sv[bb][i], p.y));
                float r = frcp(1.0f + e);
                den[bb] = fmaf(p.z, r, den[bb]);
                num[bb] = fmaf(p.w, r, num[bb]);
            }
        }

        __syncthreads();   // everyone done reading sv for this unfold
        #pragma unroll
        for (int bb = 0; bb < BB; bb++) {
            float vold  = sv[bb][j];
            float numer = fmaf(cmt, vold, gv * num[bb]);
            float denom = cmt + gl + den[bb] + EPSV;
            sv[bb][j] = numer * frcp(denom);
        }
        __syncthreads();   // new sv visible before next unfold reads
    }

    // ---- Write outputs: [outputs (B,M)] then [v_pre (B,N)] ----
    const float ow = (j < MOUT) ? output_w[j] : 0.0f;
    const float ob = (j < MOUT) ? output_b[j] : 0.0f;
    #pragma unroll
    for (int bb = 0; bb < BB; bb++) {
        float v = sv[bb][j];
        out[BATCH * MOUT + (b0 + bb) * NSTATE + j] = v;
        if (j < MOUT)
            out[(b0 + bb) * MOUT + j] = fmaf(v, ow, ob);
    }
}

extern "C" void kernel_launch(void* const* d_in, const int* in_sizes, int n_in,
                              void* d_out, int out_size)
{
    // metadata order:
    // 0 inputs, 1 states, 2 gleak, 3 vleak, 4 cm, 5 sigma, 6 mu, 7 w, 8 erev,
    // 9 sensory_sigma, 10 sensory_mu, 11 sensory_w, 12 sensory_erev,
    // 13 input_w, 14 input_b, 15 output_w, 16 output_b,
    // 17 sparsity_mask, 18 sensory_sparsity_mask
    const float* inputs   = (const float*)d_in[0];
    const float* states   = (const float*)d_in[1];
    const float* gleak    = (const float*)d_in[2];
    const float* vleak    = (const float*)d_in[3];
    const float* cm       = (const float*)d_in[4];
    const float* sigma    = (const float*)d_in[5];
    const float* mu       = (const float*)d_in[6];
    const float* w        = (const float*)d_in[7];
    const float* erev     = (const float*)d_in[8];
    const float* ssigma   = (const float*)d_in[9];
    const float* smu      = (const float*)d_in[10];
    const float* sw       = (const float*)d_in[11];
    const float* serev    = (const float*)d_in[12];
    const float* input_w  = (const float*)d_in[13];
    const float* input_b  = (const float*)d_in[14];
    const float* output_w = (const float*)d_in[15];
    const float* output_b = (const float*)d_in[16];
    const float* mask     = (const float*)d_in[17];
    const float* smask    = (const float*)d_in[18];
    float* out = (float*)d_out;

    pack_kernel<<<(NSTATE * NSTATE + 255) / 256, 256>>>(
        sigma, mu, w, erev, mask, ssigma, smu, sw, serev, smask);

    ltc_kernel<<<BATCH / BB, NSTATE>>>(
        inputs, states, gleak, vleak, cm,
        input_w, input_b, output_w, output_b, out);
}

// round 2
// speedup vs baseline: 1.1556x; 1.1556x over previous
#include <cuda_runtime.h>

#define BATCH   1024
#define SENS    128
#define NSTATE  256
#define MOUT    32
#define NUNFOLD 6
#define BB      8          // batch rows per block
#define HB      4          // batch rows per thread (BB / 2 halves)
#define EPSV    1e-8f

// Packed params for tanh-form sigmoid: sigmoid(s*(v-m)) = 0.5 + 0.5*tanh(0.5*s*(v-m))
//   x = 0.5*sigma, y = -0.5*sigma*mu, z = 0.5*w*mask, w = 0.5*w*erev*mask
__device__ float4 g_params[NSTATE * NSTATE];
__device__ float4 g_sparams[SENS * NSTATE];
// Column sums of (z, w) — the constant 0.5*Σw part of the sigmoid
__device__ float2 g_col[NSTATE];    // recurrent
__device__ float2 g_scol[NSTATE];   // sensory

__device__ __forceinline__ float ftanh(float x) {
    float y; asm("tanh.approx.f32 %0, %1;" : "=f"(y) : "f"(x)); return y;
}
__device__ __forceinline__ float frcp(float x) {
    float y; asm("rcp.approx.ftz.f32 %0, %1;" : "=f"(y) : "f"(x)); return y;
}

__global__ void pack_kernel(const float* __restrict__ sigma, const float* __restrict__ mu,
                            const float* __restrict__ w,     const float* __restrict__ erev,
                            const float* __restrict__ mask,
                            const float* __restrict__ ssigma, const float* __restrict__ smu,
                            const float* __restrict__ sw,     const float* __restrict__ serev,
                            const float* __restrict__ smask)
{
    int idx = blockIdx.x * blockDim.x + threadIdx.x;
    if (idx < NSTATE * NSTATE) {
        float sg = 0.5f * sigma[idx];
        float wm = 0.5f * w[idx] * mask[idx];
        g_params[idx] = make_float4(sg, -sg * 2.0f * mu[idx] * 0.5f * 2.0f * 0.5f // = -sg*mu
                                        , wm, w[idx] * erev[idx] * mask[idx] * 0.5f);
        // (clean form below to avoid confusion)
        g_params[idx].y = -sg * mu[idx];
    }
    if (idx < SENS * NSTATE) {
        float sg = 0.5f * ssigma[idx];
        float wm = 0.5f * sw[idx] * smask[idx];
        float4 p = make_float4(sg, -sg * smu[idx], wm, 0.5f * sw[idx] * serev[idx] * smask[idx]);
        g_sparams[idx] = p;
    }
}

// Deterministic column sums (block 0: recurrent, block 1: sensory)
__global__ void colsum_kernel()
{
    int j = threadIdx.x;
    if (blockIdx.x == 0) {
        float sz = 0.0f, sw = 0.0f;
        #pragma unroll 4
        for (int i = 0; i < NSTATE; i++) {
            float4 p = g_params[i * NSTATE + j];
            sz += p.z; sw += p.w;
        }
        g_col[j] = make_float2(sz, sw);
    } else {
        float sz = 0.0f, sw = 0.0f;
        #pragma unroll 4
        for (int s = 0; s < SENS; s++) {
            float4 p = g_sparams[s * NSTATE + j];
            sz += p.z; sw += p.w;
        }
        g_scol[j] = make_float2(sz, sw);
    }
}

__global__ __launch_bounds__(512, 1)
void ltc_kernel(const float* __restrict__ inputs, const float* __restrict__ states,
                const float* __restrict__ gleak,  const float* __restrict__ vleak,
                const float* __restrict__ cm,
                const float* __restrict__ input_w, const float* __restrict__ input_b,
                const float* __restrict__ output_w, const float* __restrict__ output_b,
                float* __restrict__ out)
{
    __shared__ float sx[BB][SENS];       // mapped sensory inputs
    __shared__ float sv[BB][NSTATE];     // current state

    const int tid = threadIdx.x;
    const int j   = tid & (NSTATE - 1);  // output neuron index
    const int h   = tid >> 8;            // batch half (0/1)
    const int bb0 = h * HB;              // first of this thread's HB batch rows
    const int b0  = blockIdx.x * BB;     // first batch row of this block

    // Load inputs with affine mapping into shared
    for (int t = tid; t < BB * SENS; t += blockDim.x) {
        int bb = t >> 7, s = t & (SENS - 1);
        sx[bb][s] = inputs[(b0 + bb) * SENS + s] * input_w[s] + input_b[s];
    }
    // Load states into shared (each half loads its own rows)
    #pragma unroll
    for (int k = 0; k < HB; k++)
        sv[bb0 + k][j] = states[(b0 + bb0 + k) * NSTATE + j];
    __syncthreads();

    // ---- Sensory synapse reduction (once) ----
    float sden[HB], snum[HB];
    #pragma unroll
    for (int k = 0; k < HB; k++) { sden[k] = 0.0f; snum[k] = 0.0f; }

    #pragma unroll 2
    for (int s = 0; s < SENS; s++) {
        float4 p = g_sparams[s * NSTATE + j];
        #pragma unroll
        for (int k = 0; k < HB; k++) {
            float t = ftanh(fmaf(p.x, sx[bb0 + k][s], p.y));
            sden[k] = fmaf(p.z, t, sden[k]);
            snum[k] = fmaf(p.w, t, snum[k]);
        }
    }
    {
        float2 sc = g_scol[j];
        #pragma unroll
        for (int k = 0; k < HB; k++) { sden[k] += sc.x; snum[k] += sc.y; }
    }

    // Per-neuron constants
    const float gl   = gleak[j];
    const float gv   = gl * vleak[j];
    const float cmt  = cm[j] * (float)NUNFOLD;   // cm / (DT/UNFOLDS), DT = 1
    const float2 col = g_col[j];
    const float dbase = sden[0];  // placeholder to keep regs tight (unused)
    (void)dbase;

    // ---- Unfold loop ----
    for (int u = 0; u < NUNFOLD; u++) {
        float den[HB], num[HB];
        #pragma unroll
        for (int k = 0; k < HB; k++) {
            den[k] = sden[k] + col.x;
            num[k] = snum[k] + col.y;
        }

        #pragma unroll 2
        for (int i = 0; i < NSTATE; i++) {
            float4 p = g_params[i * NSTATE + j];
            #pragma unroll
            for (int k = 0; k < HB; k++) {
                float t = ftanh(fmaf(p.x, sv[bb0 + k][i], p.y));
                den[k] = fmaf(p.z, t, den[k]);
                num[k] = fmaf(p.w, t, num[k]);
            }
        }

        __syncthreads();   // everyone done reading sv for this unfold
        #pragma unroll
        for (int k = 0; k < HB; k++) {
            float vold  = sv[bb0 + k][j];
            float numer = fmaf(cmt, vold, gv * num[k]);
            float denom = cmt + gl + den[k] + EPSV;
            sv[bb0 + k][j] = numer * frcp(denom);
        }
        __syncthreads();   // new sv visible before next unfold
    }

    // ---- Write outputs: [outputs (B,M)] then [v_pre (B,N)] ----
    const float ow = (j < MOUT) ? output_w[j] : 0.0f;
    const float ob = (j < MOUT) ? output_b[j] : 0.0f;
    #pragma unroll
    for (int k = 0; k < HB; k++) {
        float v = sv[bb0 + k][j];
        out[BATCH * MOUT + (b0 + bb0 + k) * NSTATE + j] = v;
        if (j < MOUT)
            out[(b0 + bb0 + k) * MOUT + j] = fmaf(v, ow, ob);
    }
}

extern "C" void kernel_launch(void* const* d_in, const int* in_sizes, int n_in,
                              void* d_out, int out_size)
{
    // metadata order:
    // 0 inputs, 1 states, 2 gleak, 3 vleak, 4 cm, 5 sigma, 6 mu, 7 w, 8 erev,
    // 9 sensory_sigma, 10 sensory_mu, 11 sensory_w, 12 sensory_erev,
    // 13 input_w, 14 input_b, 15 output_w, 16 output_b,
    // 17 sparsity_mask, 18 sensory_sparsity_mask
    const float* inputs   = (const float*)d_in[0];
    const float* states   = (const float*)d_in[1];
    const float* gleak    = (const float*)d_in[2];
    const float* vleak    = (const float*)d_in[3];
    const float* cm       = (const float*)d_in[4];
    const float* sigma    = (const float*)d_in[5];
    const float* mu       = (const float*)d_in[6];
    const float* w        = (const float*)d_in[7];
    const float* erev     = (const float*)d_in[8];
    const float* ssigma   = (const float*)d_in[9];
    const float* smu      = (const float*)d_in[10];
    const float* sw       = (const float*)d_in[11];
    const float* serev    = (const float*)d_in[12];
    const float* input_w  = (const float*)d_in[13];
    const float* input_b  = (const float*)d_in[14];
    const float* output_w = (const float*)d_in[15];
    const float* output_b = (const float*)d_in[16];
    const float* mask     = (const float*)d_in[17];
    const float* smask    = (const float*)d_in[18];
    float* out = (float*)d_out;

    pack_kernel<<<(NSTATE * NSTATE + 255) / 256, 256>>>(
        sigma, mu, w, erev, mask, ssigma, smu, sw, serev, smask);

    colsum_kernel<<<2, NSTATE>>>();

    ltc_kernel<<<BATCH / BB, 512>>>(
        inputs, states, gleak, vleak, cm,
        input_w, input_b, output_w, output_b, out);
}